// round 10
// baseline (speedup 1.0000x reference)
#include <cuda_runtime.h>
#include <cuda_fp16.h>
#include <cstdint>

static constexpr int SEQ = 4096;
static constexpr int DM  = 1024;
static constexpr int NH  = 16;
static constexpr int HD  = 64;

#define QSCALE 0.18033688011112042f  // 0.125 * log2(e)

// Scratch (allocation-free rule: device globals). All fp16.
__device__ __half g_q[SEQ * DM];
__device__ __half g_k[SEQ * DM];
__device__ __half g_v[SEQ * DM];
__device__ __half g_ctx[SEQ * DM];
__device__ __half g_xh[SEQ * DM];
__device__ __half g_wqh[DM * DM];
__device__ __half g_wkh[DM * DM];
__device__ __half g_wvh[DM * DM];
__device__ __half g_woh[DM * DM];

__device__ __forceinline__ float ex2f(float x) {
    float y;
    asm("ex2.approx.f32 %0, %1;" : "=f"(y) : "f"(x));
    return y;
}
__device__ __forceinline__ uint32_t h2u(__half2 h) { return *(uint32_t*)&h; }

__device__ __forceinline__ void mma_f16(float* d, const uint32_t* a, const uint32_t* b) {
    asm volatile(
        "mma.sync.aligned.m16n8k16.row.col.f32.f16.f16.f32 "
        "{%0,%1,%2,%3}, {%4,%5,%6,%7}, {%8,%9}, {%0,%1,%2,%3};"
        : "+f"(d[0]), "+f"(d[1]), "+f"(d[2]), "+f"(d[3])
        : "r"(a[0]), "r"(a[1]), "r"(a[2]), "r"(a[3]), "r"(b[0]), "r"(b[1]));
}

__device__ __forceinline__ uint32_t smem_u32(const void* p) {
    uint32_t a;
    asm("{ .reg .u64 t; cvta.to.shared.u64 t, %1; cvt.u32.u64 %0, t; }"
        : "=r"(a) : "l"(p));
    return a;
}

__device__ __forceinline__ void ldsm_x4(uint32_t* r, uint32_t addr) {
    asm volatile("ldmatrix.sync.aligned.m8n8.x4.shared.b16 {%0,%1,%2,%3}, [%4];"
                 : "=r"(r[0]), "=r"(r[1]), "=r"(r[2]), "=r"(r[3]) : "r"(addr));
}
__device__ __forceinline__ void ldsm_x2(uint32_t* r, uint32_t addr) {
    asm volatile("ldmatrix.sync.aligned.m8n8.x2.shared.b16 {%0,%1}, [%2];"
                 : "=r"(r[0]), "=r"(r[1]) : "r"(addr));
}
__device__ __forceinline__ void ldsm_x2t(uint32_t* r, uint32_t addr) {
    asm volatile("ldmatrix.sync.aligned.m8n8.x2.trans.shared.b16 {%0,%1}, [%2];"
                 : "=r"(r[0]), "=r"(r[1]) : "r"(addr));
}

__device__ __forceinline__ void cp16(uint32_t dst, const void* src) {
    asm volatile("cp.async.cg.shared.global [%0], [%1], 16;" :: "r"(dst), "l"(src));
}
#define CP_COMMIT() asm volatile("cp.async.commit_group;" ::: "memory")
#define CP_WAIT0()  asm volatile("cp.async.wait_group 0;" ::: "memory")
#define CP_WAIT1()  asm volatile("cp.async.wait_group 1;" ::: "memory")

// ---------------------------------------------------------------------------
// Prep: fp32 -> fp16 (rn) for x and the four weights.
// ---------------------------------------------------------------------------
__global__ void __launch_bounds__(256) cvt_prep(const float* __restrict__ x,
                                                const float* __restrict__ wq,
                                                const float* __restrict__ wk,
                                                const float* __restrict__ wv,
                                                const float* __restrict__ wo) {
    const int z = blockIdx.z;
    const int idx = blockIdx.x * 256 + threadIdx.x;
    constexpr int MSEG = 1024 * 1024;
    const float* src;
    __half* dst;
    if (z < 4)       { src = x + (size_t)z * MSEG; dst = g_xh + (size_t)z * MSEG; }
    else if (z == 4) { src = wq; dst = g_wqh; }
    else if (z == 5) { src = wk; dst = g_wkh; }
    else if (z == 6) { src = wv; dst = g_wvh; }
    else             { src = wo; dst = g_woh; }
    float4 v = ((const float4*)src)[idx];
    ((uint2*)dst)[idx] = make_uint2(h2u(__floats2half2_rn(v.x, v.y)),
                                    h2u(__floats2half2_rn(v.z, v.w)));
}

// ---------------------------------------------------------------------------
// FP16 GEMM (NT): C[m,n] = sum_k A[m,k]*B[n,k], fp32 accumulate.
// BM=BN=128, BK=64 halves per iteration (one barrier per BK=64).
// 8 warps 2(M)x4(N), warp 64x32. 3-stage cp.async pipeline.
// Row stride 36 words (32 data + 4 pad): ldmatrix conflict-free (proven in
// the R8 attention kernel with the same stride).
// ---------------------------------------------------------------------------
static constexpr int G_ST   = 36;                   // words per row
static constexpr int G_TW   = 128 * G_ST;           // words per operand tile (4608)
static constexpr int G_STG  = 2 * G_TW;             // words per stage (9216)
static constexpr int G_SMEM = 3 * G_STG * 4;        // 110592 bytes
static constexpr int G_NIT  = DM / 64;              // 16

template <bool CVT_OUT>
__global__ void __launch_bounds__(256, 2)
gemm_f16(const __half* __restrict__ A,
         const __half* __restrict__ B0, const __half* __restrict__ B1,
         const __half* __restrict__ B2,
         void* __restrict__ C0, void* __restrict__ C1, void* __restrict__ C2,
         float scale0) {
    extern __shared__ uint32_t smg[];

    const __half* B = (blockIdx.z == 0) ? B0 : (blockIdx.z == 1 ? B1 : B2);
    void*         C = (blockIdx.z == 0) ? C0 : (blockIdx.z == 1 ? C1 : C2);
    const float oscale = (blockIdx.z == 0) ? scale0 : 1.0f;

    const int tid  = threadIdx.x;
    const int warp = tid >> 5;
    const int lane = tid & 31;
    const int grp  = lane >> 2;
    const int lq   = lane & 3;
    const int ln16 = lane & 15;
    const int hi16 = lane >> 4;
    const int ln8  = lane & 7;
    const int bhi  = (lane >> 3) & 1;
    const int wm0  = (warp & 1) * 64;    // 2 m-warps
    const int wn0  = (warp >> 1) * 32;   // 4 n-warps

    const int bm = blockIdx.y * 128;
    const int bn = blockIdx.x * 128;

    // staging: row = tid>>1 (0..127), half-range (tid&1)*32 halves (4 cp16)
    const int row = tid >> 1;
    const int hh  = tid & 1;
    const __half* Ag = A + (size_t)(bm + row) * DM + hh * 32;
    const __half* Bg = B + (size_t)(bn + row) * DM + hh * 32;
    const uint32_t smb = smem_u32(smg);
    const uint32_t a_sm = smb + (uint32_t)(row * G_ST + hh * 16) * 4;
    const uint32_t b_sm = a_sm + (uint32_t)G_TW * 4;

#define G_ISSUE(it, stg)                                                      \
    do {                                                                      \
        const __half* ap = Ag + (size_t)(it) * 64;                            \
        const __half* bp = Bg + (size_t)(it) * 64;                            \
        uint32_t so = (uint32_t)(stg) * G_STG * 4;                            \
        cp16(a_sm + so,      ap);      cp16(a_sm + so + 16, ap + 8);          \
        cp16(a_sm + so + 32, ap + 16); cp16(a_sm + so + 48, ap + 24);         \
        cp16(b_sm + so,      bp);      cp16(b_sm + so + 16, bp + 8);          \
        cp16(b_sm + so + 32, bp + 16); cp16(b_sm + so + 48, bp + 24);         \
        CP_COMMIT();                                                          \
    } while (0)

    G_ISSUE(0, 0);
    G_ISSUE(1, 1);

    float acc[4][4][4] = {};

#pragma unroll 1
    for (int i = 0; i < G_NIT; ++i) {
        if (i == G_NIT - 1) { CP_WAIT0(); } else { CP_WAIT1(); }
        __syncthreads();
        if (i + 2 < G_NIT) G_ISSUE(i + 2, (i + 2) % 3);

        const uint32_t sA = smb + (uint32_t)(i % 3) * G_STG * 4;
        const uint32_t sB = sA + (uint32_t)G_TW * 4;

#pragma unroll
        for (int kt = 0; kt < 4; ++kt) {
            uint32_t afr[4][4];
#pragma unroll
            for (int im = 0; im < 4; ++im)
                ldsm_x4(afr[im],
                        sA + (uint32_t)((wm0 + im * 16 + ln16) * G_ST + kt * 8 + hi16 * 4) * 4);
#pragma unroll
            for (int in = 0; in < 4; ++in) {
                uint32_t bfr[2];
                ldsm_x2(bfr,
                        sB + (uint32_t)((wn0 + in * 8 + ln8) * G_ST + kt * 8 + bhi * 4) * 4);
#pragma unroll
                for (int im = 0; im < 4; ++im)
                    mma_f16(acc[im][in], afr[im], bfr);
            }
        }
    }
#undef G_ISSUE

#pragma unroll
    for (int im = 0; im < 4; ++im) {
#pragma unroll
        for (int in = 0; in < 4; ++in) {
            size_t row0 = (size_t)(bm + wm0 + im * 16 + grp);
            int col = bn + wn0 + in * 8 + 2 * lq;
            if (CVT_OUT) {
                __half* Ch = (__half*)C;
                __half2 lo = __floats2half2_rn(acc[im][in][0] * oscale,
                                               acc[im][in][1] * oscale);
                __half2 hi = __floats2half2_rn(acc[im][in][2] * oscale,
                                               acc[im][in][3] * oscale);
                *(uint32_t*)&Ch[row0 * DM + col]       = h2u(lo);
                *(uint32_t*)&Ch[(row0 + 8) * DM + col] = h2u(hi);
            } else {
                float* Cf = (float*)C;
                *(float2*)&Cf[row0 * DM + col] =
                    make_float2(acc[im][in][0], acc[im][in][1]);
                *(float2*)&Cf[(row0 + 8) * DM + col] =
                    make_float2(acc[im][in][2], acc[im][in][3]);
            }
        }
    }
}

// ---------------------------------------------------------------------------
// Flash attention, fp16 MMA m16n8k16. q-tile 128, kv-block 128 per barrier
// (two 64-row halves back-to-back), 8 warps x m16. No-max base-2 softmax.
// cp.async double-buffered K/V (128-row stages). V via ldmatrix.trans.
// Smem: Qs[128][36w] | stages[2] x (K[128][36w] + V[128][36w])  (90 KB)
// ---------------------------------------------------------------------------
static constexpr int A_ST   = 36;
static constexpr int A_QW   = 128 * A_ST;                 // 4608 words
static constexpr int A_TW   = 128 * A_ST;                 // K or V tile words
static constexpr int A_STG  = 2 * A_TW;                   // stage words (9216)
static constexpr int A_SMEM = (A_QW + 2 * A_STG) * 4;     // 92160 bytes

__global__ void __launch_bounds__(256, 2) attn_f16(const __half* __restrict__ Q,
                                                   const __half* __restrict__ K,
                                                   const __half* __restrict__ V,
                                                   __half* __restrict__ O) {
    extern __shared__ uint32_t sm[];

    const int tid  = threadIdx.x;
    const int lane = tid & 31;
    const int grp  = lane >> 2;
    const int lq   = lane & 3;
    const int ln16 = lane & 15;
    const int hi16 = lane >> 4;
    const int ln8  = lane & 7;
    const int bhi  = (lane >> 3) & 1;
    const int head = blockIdx.y;
    const int qt   = (int)gridDim.x - 1 - (int)blockIdx.x;  // long CTAs first
    const int qrow0 = qt * 128;
    const int col0  = head * HD;
    const int w16   = (tid >> 5) * 16;

    const uint32_t smb = smem_u32(sm);

    // staging maps: row = tid>>1 (0..127), 32-half chunk hh = tid&1
    const int row = tid >> 1;
    const int hh  = tid & 1;
    const __half* Ksrc = K + (size_t)row * DM + col0 + hh * 32;
    const __half* Vsrc = V + (size_t)row * DM + col0 + hh * 32;
    const uint32_t ksd = smb + (uint32_t)(A_QW + row * A_ST + hh * 16) * 4;
    const uint32_t vsd = ksd + (uint32_t)A_TW * 4;

    // ---- Prologue: Q tile + K(0),V(0) as group 0 ----
    {
        const __half* qs = Q + (size_t)(qrow0 + row) * DM + col0 + hh * 32;
        uint32_t qd = smb + (uint32_t)(row * A_ST + hh * 16) * 4;
#pragma unroll
        for (int p = 0; p < 4; ++p) cp16(qd + p * 16, qs + p * 8);
#pragma unroll
        for (int p = 0; p < 4; ++p) {
            cp16(ksd + p * 16, Ksrc + p * 8);
            cp16(vsd + p * 16, Vsrc + p * 8);
        }
        CP_COMMIT();
    }

    float Oa[8][4];
    float l_s[2] = {0.0f, 0.0f};
#pragma unroll
    for (int nt = 0; nt < 8; ++nt)
#pragma unroll
        for (int c = 0; c < 4; ++c) Oa[nt][c] = 0.0f;

    const int nkb = qt + 1;   // 128-row kv blocks
    for (int kb = 0; kb < nkb; ++kb) {
        CP_WAIT0();
        __syncthreads();

        if (kb + 1 < nkb) {
            const int b = (kb + 1) & 1;
            const __half* Kp = Ksrc + (size_t)(kb + 1) * 128 * DM;
            const __half* Vp = Vsrc + (size_t)(kb + 1) * 128 * DM;
            const uint32_t kd = ksd + (uint32_t)(b * A_STG) * 4;
            const uint32_t vd = vsd + (uint32_t)(b * A_STG) * 4;
#pragma unroll
            for (int p = 0; p < 4; ++p) {
                cp16(kd + p * 16, Kp + p * 8);
                cp16(vd + p * 16, Vp + p * 8);
            }
            CP_COMMIT();
        }

        const uint32_t sK = smb + (uint32_t)(A_QW + (kb & 1) * A_STG) * 4;
        const uint32_t sV = sK + (uint32_t)A_TW * 4;
        const bool diag = (kb == qt);

#pragma unroll
        for (int h = 0; h < 2; ++h) {
            const uint32_t sKh = sK + (uint32_t)(h * 64 * A_ST) * 4;
            const uint32_t sVh = sV + (uint32_t)(h * 64 * A_ST) * 4;

            // ---- S = Q K^T ----
            float S[8][4];
#pragma unroll
            for (int nt = 0; nt < 8; ++nt)
#pragma unroll
                for (int c = 0; c < 4; ++c) S[nt][c] = 0.0f;

#pragma unroll
            for (int kt = 0; kt < 4; ++kt) {
                uint32_t a[4];
                ldsm_x4(a, smb + (uint32_t)((w16 + ln16) * A_ST + kt * 8 + hi16 * 4) * 4);
#pragma unroll
                for (int nt = 0; nt < 8; ++nt) {
                    uint32_t b[2];
                    ldsm_x2(b, sKh + (uint32_t)((nt * 8 + ln8) * A_ST + kt * 8 + bhi * 4) * 4);
                    mma_f16(S[nt], a, b);
                }
            }

            // ---- Causal mask (diagonal 128-block only) ----
            if (diag) {
#pragma unroll
                for (int nt = 0; nt < 8; ++nt)
#pragma unroll
                    for (int c = 0; c < 4; ++c) {
                        int qi = qrow0 + w16 + grp + ((c >> 1) << 3);
                        int kj = kb * 128 + h * 64 + nt * 8 + 2 * lq + (c & 1);
                        if (kj > qi) S[nt][c] = -10000.0f;
                    }
            }

            // ---- p = 2^s; accumulate l ----
#pragma unroll
            for (int nt = 0; nt < 8; ++nt) {
                float p0 = ex2f(S[nt][0]);
                float p1 = ex2f(S[nt][1]);
                float p2 = ex2f(S[nt][2]);
                float p3 = ex2f(S[nt][3]);
                l_s[0] += p0 + p1;
                l_s[1] += p2 + p3;
                S[nt][0] = p0; S[nt][1] = p1; S[nt][2] = p2; S[nt][3] = p3;
            }

            // ---- O += P V ----
#pragma unroll
            for (int kt = 0; kt < 4; ++kt) {
                uint32_t a[4];
                a[0] = h2u(__floats2half2_rn(S[2 * kt][0],     S[2 * kt][1]));
                a[1] = h2u(__floats2half2_rn(S[2 * kt][2],     S[2 * kt][3]));
                a[2] = h2u(__floats2half2_rn(S[2 * kt + 1][0], S[2 * kt + 1][1]));
                a[3] = h2u(__floats2half2_rn(S[2 * kt + 1][2], S[2 * kt + 1][3]));
                const uint32_t rowaddr = sVh + (uint32_t)((kt * 16 + ln16) * A_ST) * 4;
#pragma unroll
                for (int nt = 0; nt < 8; ++nt) {
                    uint32_t b[2];
                    ldsm_x2t(b, rowaddr + nt * 16);
                    mma_f16(Oa[nt], a, b);
                }
            }
        }
    }

    // ---- Final l reduction + writeback ----
    l_s[0] += __shfl_xor_sync(0xffffffffu, l_s[0], 1);
    l_s[0] += __shfl_xor_sync(0xffffffffu, l_s[0], 2);
    l_s[1] += __shfl_xor_sync(0xffffffffu, l_s[1], 1);
    l_s[1] += __shfl_xor_sync(0xffffffffu, l_s[1], 2);
    const float inv0 = 1.0f / l_s[0];
    const float inv1 = 1.0f / l_s[1];
    {
        size_t orow = (size_t)(qrow0 + w16 + grp);
#pragma unroll
        for (int nt = 0; nt < 8; ++nt) {
            int col = col0 + nt * 8 + 2 * lq;
            __half2 lo = __floats2half2_rn(Oa[nt][0] * inv0, Oa[nt][1] * inv0);
            __half2 hi = __floats2half2_rn(Oa[nt][2] * inv1, Oa[nt][3] * inv1);
            *(uint32_t*)&O[orow * DM + col]       = h2u(lo);
            *(uint32_t*)&O[(orow + 8) * DM + col] = h2u(hi);
        }
    }
}

// ---------------------------------------------------------------------------
extern "C" void kernel_launch(void* const* d_in, const int* in_sizes, int n_in,
                              void* d_out, int out_size) {
    const float* x  = (const float*)d_in[0];
    const float* wq = (const float*)d_in[1];
    const float* wk = (const float*)d_in[2];
    const float* wv = (const float*)d_in[3];
    const float* wo = (const float*)d_in[4];
    float* out = (float*)d_out;

    __half *q, *k, *v, *ctx, *xh, *wqh, *wkh, *wvh, *woh;
    cudaGetSymbolAddress((void**)&q,   g_q);
    cudaGetSymbolAddress((void**)&k,   g_k);
    cudaGetSymbolAddress((void**)&v,   g_v);
    cudaGetSymbolAddress((void**)&ctx, g_ctx);
    cudaGetSymbolAddress((void**)&xh,  g_xh);
    cudaGetSymbolAddress((void**)&wqh, g_wqh);
    cudaGetSymbolAddress((void**)&wkh, g_wkh);
    cudaGetSymbolAddress((void**)&wvh, g_wvh);
    cudaGetSymbolAddress((void**)&woh, g_woh);

    cudaFuncSetAttribute(attn_f16, cudaFuncAttributeMaxDynamicSharedMemorySize,
                         A_SMEM);
    cudaFuncSetAttribute(gemm_f16<true>,
                         cudaFuncAttributeMaxDynamicSharedMemorySize, G_SMEM);
    cudaFuncSetAttribute(gemm_f16<false>,
                         cudaFuncAttributeMaxDynamicSharedMemorySize, G_SMEM);

    // 1) fp32 -> fp16 conversion of x + weights
    cvt_prep<<<dim3(1024, 1, 8), 256>>>(x, wq, wk, wv, wo);

    // 2) fused QKV projection
    dim3 qkv_grid(DM / 128, SEQ / 128, 3);
    gemm_f16<true><<<qkv_grid, 256, G_SMEM>>>(xh, wqh, wkh, wvh, q, k, v, QSCALE);

    // 3) attention
    attn_f16<<<dim3(SEQ / 128, NH), 256, A_SMEM>>>(q, k, v, ctx);

    // 4) output projection (fp32 out)
    dim3 wo_grid(DM / 128, SEQ / 128, 1);
    gemm_f16<false><<<wo_grid, 256, G_SMEM>>>(ctx, woh, woh, woh, out, out, out, 1.0f);
}

// round 11
// speedup vs baseline: 1.1094x; 1.1094x over previous
#include <cuda_runtime.h>
#include <cuda_fp16.h>
#include <cstdint>

static constexpr int SEQ = 4096;
static constexpr int DM  = 1024;
static constexpr int NH  = 16;
static constexpr int HD  = 64;

#define QSCALE 0.18033688011112042f  // 0.125 * log2(e)

// Scratch (allocation-free rule: device globals). All fp16.
__device__ __half g_q[SEQ * DM];
__device__ __half g_k[SEQ * DM];
__device__ __half g_v[SEQ * DM];
__device__ __half g_ctx[SEQ * DM];
__device__ __half g_xh[SEQ * DM];
__device__ __half g_wqh[DM * DM];
__device__ __half g_wkh[DM * DM];
__device__ __half g_wvh[DM * DM];
__device__ __half g_woh[DM * DM];

__device__ __forceinline__ float ex2f(float x) {
    float y;
    asm("ex2.approx.f32 %0, %1;" : "=f"(y) : "f"(x));
    return y;
}
__device__ __forceinline__ uint32_t h2u(__half2 h) { return *(uint32_t*)&h; }

__device__ __forceinline__ void mma_f16(float* d, const uint32_t* a, const uint32_t* b) {
    asm volatile(
        "mma.sync.aligned.m16n8k16.row.col.f32.f16.f16.f32 "
        "{%0,%1,%2,%3}, {%4,%5,%6,%7}, {%8,%9}, {%0,%1,%2,%3};"
        : "+f"(d[0]), "+f"(d[1]), "+f"(d[2]), "+f"(d[3])
        : "r"(a[0]), "r"(a[1]), "r"(a[2]), "r"(a[3]), "r"(b[0]), "r"(b[1]));
}

__device__ __forceinline__ uint32_t smem_u32(const void* p) {
    uint32_t a;
    asm("{ .reg .u64 t; cvta.to.shared.u64 t, %1; cvt.u32.u64 %0, t; }"
        : "=r"(a) : "l"(p));
    return a;
}

__device__ __forceinline__ void ldsm_x4(uint32_t* r, uint32_t addr) {
    asm volatile("ldmatrix.sync.aligned.m8n8.x4.shared.b16 {%0,%1,%2,%3}, [%4];"
                 : "=r"(r[0]), "=r"(r[1]), "=r"(r[2]), "=r"(r[3]) : "r"(addr));
}
__device__ __forceinline__ void ldsm_x2(uint32_t* r, uint32_t addr) {
    asm volatile("ldmatrix.sync.aligned.m8n8.x2.shared.b16 {%0,%1}, [%2];"
                 : "=r"(r[0]), "=r"(r[1]) : "r"(addr));
}
__device__ __forceinline__ void ldsm_x2t(uint32_t* r, uint32_t addr) {
    asm volatile("ldmatrix.sync.aligned.m8n8.x2.trans.shared.b16 {%0,%1}, [%2];"
                 : "=r"(r[0]), "=r"(r[1]) : "r"(addr));
}

__device__ __forceinline__ void cp16(uint32_t dst, const void* src) {
    asm volatile("cp.async.cg.shared.global [%0], [%1], 16;" :: "r"(dst), "l"(src));
}
#define CP_COMMIT() asm volatile("cp.async.commit_group;" ::: "memory")
#define CP_WAIT0()  asm volatile("cp.async.wait_group 0;" ::: "memory")
#define CP_WAIT1()  asm volatile("cp.async.wait_group 1;" ::: "memory")
#define CP_WAIT2()  asm volatile("cp.async.wait_group 2;" ::: "memory")
#define CP_WAIT3()  asm volatile("cp.async.wait_group 3;" ::: "memory")

// ---------------------------------------------------------------------------
// Prep: fp32 -> fp16 (rn) for x and the four weights.
// ---------------------------------------------------------------------------
__global__ void __launch_bounds__(256) cvt_prep(const float* __restrict__ x,
                                                const float* __restrict__ wq,
                                                const float* __restrict__ wk,
                                                const float* __restrict__ wv,
                                                const float* __restrict__ wo) {
    const int z = blockIdx.z;
    const int idx = blockIdx.x * 256 + threadIdx.x;
    constexpr int MSEG = 1024 * 1024;
    const float* src;
    __half* dst;
    if (z < 4)       { src = x + (size_t)z * MSEG; dst = g_xh + (size_t)z * MSEG; }
    else if (z == 4) { src = wq; dst = g_wqh; }
    else if (z == 5) { src = wk; dst = g_wkh; }
    else if (z == 6) { src = wv; dst = g_wvh; }
    else             { src = wo; dst = g_woh; }
    float4 v = ((const float4*)src)[idx];
    ((uint2*)dst)[idx] = make_uint2(h2u(__floats2half2_rn(v.x, v.y)),
                                    h2u(__floats2half2_rn(v.z, v.w)));
}

// ---------------------------------------------------------------------------
// FP16 GEMM (NT): C[m,n] = sum_k A[m,k]*B[n,k], fp32 accumulate.
// BM=BN=128, BK=32 halves, 8 warps 2(M)x4(N), warp 64x32.
// 5-stage cp.async pipeline (prefetch distance 4 iters), one barrier/iter.
// Row stride 20 words: ldmatrix conflict-free (proven R8).
// ---------------------------------------------------------------------------
static constexpr int G_ST    = 20;                   // words per row
static constexpr int G_STA   = 128 * G_ST;           // 2560 words per operand tile
static constexpr int G_STG   = 2 * G_STA;            // 5120 words per stage
static constexpr int G_NSTG  = 5;
static constexpr int G_SMEM  = G_NSTG * G_STG * 4;   // 102400 bytes
static constexpr int G_NIT   = DM / 32;              // 32

template <bool CVT_OUT>
__global__ void __launch_bounds__(256, 2)
gemm_f16(const __half* __restrict__ A,
         const __half* __restrict__ B0, const __half* __restrict__ B1,
         const __half* __restrict__ B2,
         void* __restrict__ C0, void* __restrict__ C1, void* __restrict__ C2,
         float scale0) {
    extern __shared__ uint32_t smg[];

    const __half* B = (blockIdx.z == 0) ? B0 : (blockIdx.z == 1 ? B1 : B2);
    void*         C = (blockIdx.z == 0) ? C0 : (blockIdx.z == 1 ? C1 : C2);
    const float oscale = (blockIdx.z == 0) ? scale0 : 1.0f;

    const int tid  = threadIdx.x;
    const int warp = tid >> 5;
    const int lane = tid & 31;
    const int grp  = lane >> 2;
    const int lq   = lane & 3;
    const int ln16 = lane & 15;
    const int hi16 = lane >> 4;
    const int ln8  = lane & 7;
    const int bhi  = (lane >> 3) & 1;
    const int wm0  = (warp & 1) * 64;    // 2 m-warps
    const int wn0  = (warp >> 1) * 32;   // 4 n-warps

    const int bm = blockIdx.y * 128;
    const int bn = blockIdx.x * 128;

    // staging: thread -> (row tid>>1, 16-half chunk (tid&1))
    const __half* Ag = A + (size_t)(bm + (tid >> 1)) * DM + (tid & 1) * 16;
    const __half* Bg = B + (size_t)(bn + (tid >> 1)) * DM + (tid & 1) * 16;
    const uint32_t smb = smem_u32(smg);
    const uint32_t a_sm = smb + (uint32_t)((tid >> 1) * G_ST + (tid & 1) * 8) * 4;
    const uint32_t b_sm = a_sm + (uint32_t)G_STA * 4;

#define G_ISSUE(it, stg)                                                      \
    do {                                                                      \
        const __half* ap = Ag + (size_t)(it) * 32;                            \
        const __half* bp = Bg + (size_t)(it) * 32;                            \
        uint32_t so = (uint32_t)(stg) * G_STG * 4;                            \
        cp16(a_sm + so, ap); cp16(a_sm + so + 16, ap + 8);                    \
        cp16(b_sm + so, bp); cp16(b_sm + so + 16, bp + 8);                    \
        CP_COMMIT();                                                          \
    } while (0)

    G_ISSUE(0, 0);
    G_ISSUE(1, 1);
    G_ISSUE(2, 2);
    G_ISSUE(3, 3);

    float acc[4][4][4] = {};

#pragma unroll 1
    for (int i = 0; i < G_NIT; ++i) {
        {
            const int rem = G_NIT - 1 - i;   // groups still outstanding beyond i
            if (rem >= 3)      { CP_WAIT3(); }
            else if (rem == 2) { CP_WAIT2(); }
            else if (rem == 1) { CP_WAIT1(); }
            else               { CP_WAIT0(); }
        }
        __syncthreads();
        if (i + 4 < G_NIT) G_ISSUE(i + 4, (i + 4) % G_NSTG);

        const uint32_t sA = smb + (uint32_t)(i % G_NSTG) * G_STG * 4;
        const uint32_t sB = sA + (uint32_t)G_STA * 4;

#pragma unroll
        for (int s = 0; s < 2; ++s) {
            uint32_t afr[4][4];
#pragma unroll
            for (int im = 0; im < 4; ++im)
                ldsm_x4(afr[im],
                        sA + (uint32_t)((wm0 + im * 16 + ln16) * G_ST + s * 8 + hi16 * 4) * 4);
#pragma unroll
            for (int in = 0; in < 4; ++in) {
                uint32_t bfr[2];
                ldsm_x2(bfr,
                        sB + (uint32_t)((wn0 + in * 8 + ln8) * G_ST + s * 8 + bhi * 4) * 4);
#pragma unroll
                for (int im = 0; im < 4; ++im)
                    mma_f16(acc[im][in], afr[im], bfr);
            }
        }
    }
#undef G_ISSUE

#pragma unroll
    for (int im = 0; im < 4; ++im) {
#pragma unroll
        for (int in = 0; in < 4; ++in) {
            size_t row0 = (size_t)(bm + wm0 + im * 16 + grp);
            int col = bn + wn0 + in * 8 + 2 * lq;
            if (CVT_OUT) {
                __half* Ch = (__half*)C;
                __half2 lo = __floats2half2_rn(acc[im][in][0] * oscale,
                                               acc[im][in][1] * oscale);
                __half2 hi = __floats2half2_rn(acc[im][in][2] * oscale,
                                               acc[im][in][3] * oscale);
                *(uint32_t*)&Ch[row0 * DM + col]       = h2u(lo);
                *(uint32_t*)&Ch[(row0 + 8) * DM + col] = h2u(hi);
            } else {
                float* Cf = (float*)C;
                *(float2*)&Cf[row0 * DM + col] =
                    make_float2(acc[im][in][0], acc[im][in][1]);
                *(float2*)&Cf[(row0 + 8) * DM + col] =
                    make_float2(acc[im][in][2], acc[im][in][3]);
            }
        }
    }
}

// ---------------------------------------------------------------------------
// Flash attention, fp16 MMA m16n8k16 (R8 structure), kv-tile 64,
// 3-stage cp.async K/V pipeline (prefetch distance 2 kv-blocks).
// Smem: Qs[128][36w] | stages[3] x (K[64][36w] + V[64][36w])  (72 KB)
// ---------------------------------------------------------------------------
static constexpr int A_ST   = 36;
static constexpr int A_QW   = 128 * A_ST;                 // 4608 words
static constexpr int A_KVW  = 64 * A_ST;                  // 2304 words per tile
static constexpr int A_STG  = 2 * A_KVW;                  // K+V stage words
static constexpr int A_SMEM = (A_QW + 3 * A_STG) * 4;     // 73728 bytes

__global__ void __launch_bounds__(256, 2) attn_f16(const __half* __restrict__ Q,
                                                   const __half* __restrict__ K,
                                                   const __half* __restrict__ V,
                                                   __half* __restrict__ O) {
    extern __shared__ uint32_t sm[];

    const int tid  = threadIdx.x;
    const int lane = tid & 31;
    const int grp  = lane >> 2;
    const int lq   = lane & 3;
    const int ln16 = lane & 15;
    const int hi16 = lane >> 4;
    const int ln8  = lane & 7;
    const int bhi  = (lane >> 3) & 1;
    const int head = blockIdx.y;
    const int qt   = (int)gridDim.x - 1 - (int)blockIdx.x;  // long CTAs first
    const int qrow0 = qt * 128;
    const int col0  = head * HD;
    const int w16   = (tid >> 5) * 16;

    const uint32_t smb = smem_u32(sm);

    // staging maps: 4 threads per kv row (16 halves each)
    const int krow = tid >> 2;
    const int kch  = (tid & 3) * 16;
    const __half* Ksrc = K + (size_t)krow * DM + col0 + kch;
    const __half* Vsrc = V + (size_t)krow * DM + col0 + kch;
    const uint32_t ksd = smb + (uint32_t)(A_QW + krow * A_ST + (tid & 3) * 8) * 4;
    const uint32_t vsd = ksd + (uint32_t)A_KVW * 4;

    const int nkb = 2 * qt + 2;

#define A_ISSUE(kb_, stg)                                                     \
    do {                                                                      \
        const __half* Kp = Ksrc + (size_t)(kb_) * 64 * DM;                    \
        const __half* Vp = Vsrc + (size_t)(kb_) * 64 * DM;                    \
        const uint32_t so = (uint32_t)((stg) * A_STG) * 4;                    \
        cp16(ksd + so, Kp); cp16(ksd + so + 16, Kp + 8);                      \
        cp16(vsd + so, Vp); cp16(vsd + so + 16, Vp + 8);                      \
        CP_COMMIT();                                                          \
    } while (0)

    // ---- Prologue: Q tile + K/V(0) as group 0; K/V(1) as group 1 ----
    {
        int qrow = tid >> 1;
        const __half* qs = Q + (size_t)(qrow0 + qrow) * DM + col0 + (tid & 1) * 32;
        uint32_t qd = smb + (uint32_t)(qrow * A_ST + (tid & 1) * 16) * 4;
#pragma unroll
        for (int p = 0; p < 4; ++p) cp16(qd + p * 16, qs + p * 8);
    }
    A_ISSUE(0, 0);      // group 0 (includes Q copies above)
    A_ISSUE(1, 1);      // group 1

    float Oa[8][4];
    float l_s[2] = {0.0f, 0.0f};
#pragma unroll
    for (int nt = 0; nt < 8; ++nt)
#pragma unroll
        for (int c = 0; c < 4; ++c) Oa[nt][c] = 0.0f;

    for (int kb = 0; kb < nkb; ++kb) {
        if (kb < nkb - 1) { CP_WAIT1(); } else { CP_WAIT0(); }
        __syncthreads();
        if (kb + 2 < nkb) A_ISSUE(kb + 2, (kb + 2) % 3);

        const uint32_t sK = smb + (uint32_t)(A_QW + (kb % 3) * A_STG) * 4;
        const uint32_t sV = sK + (uint32_t)A_KVW * 4;

        // ---- S = Q K^T ----
        float S[8][4];
#pragma unroll
        for (int nt = 0; nt < 8; ++nt)
#pragma unroll
            for (int c = 0; c < 4; ++c) S[nt][c] = 0.0f;

#pragma unroll
        for (int kt = 0; kt < 4; ++kt) {
            uint32_t a[4];
            ldsm_x4(a, smb + (uint32_t)((w16 + ln16) * A_ST + kt * 8 + hi16 * 4) * 4);
#pragma unroll
            for (int nt = 0; nt < 8; ++nt) {
                uint32_t b[2];
                ldsm_x2(b, sK + (uint32_t)((nt * 8 + ln8) * A_ST + kt * 8 + bhi * 4) * 4);
                mma_f16(S[nt], a, b);
            }
        }

        // ---- Causal mask (last two kv blocks of the tile) ----
        if (kb >= 2 * qt) {
#pragma unroll
            for (int nt = 0; nt < 8; ++nt)
#pragma unroll
                for (int c = 0; c < 4; ++c) {
                    int qi = qrow0 + w16 + grp + ((c >> 1) << 3);
                    int kj = kb * 64 + nt * 8 + 2 * lq + (c & 1);
                    if (kj > qi) S[nt][c] = -10000.0f;
                }
        }

        // ---- p = 2^s; accumulate l ----
#pragma unroll
        for (int nt = 0; nt < 8; ++nt) {
            float p0 = ex2f(S[nt][0]);
            float p1 = ex2f(S[nt][1]);
            float p2 = ex2f(S[nt][2]);
            float p3 = ex2f(S[nt][3]);
            l_s[0] += p0 + p1;
            l_s[1] += p2 + p3;
            S[nt][0] = p0; S[nt][1] = p1; S[nt][2] = p2; S[nt][3] = p3;
        }

        // ---- O += P V ----
#pragma unroll
        for (int kt = 0; kt < 4; ++kt) {
            uint32_t a[4];
            a[0] = h2u(__floats2half2_rn(S[2 * kt][0],     S[2 * kt][1]));
            a[1] = h2u(__floats2half2_rn(S[2 * kt][2],     S[2 * kt][3]));
            a[2] = h2u(__floats2half2_rn(S[2 * kt + 1][0], S[2 * kt + 1][1]));
            a[3] = h2u(__floats2half2_rn(S[2 * kt + 1][2], S[2 * kt + 1][3]));
            const uint32_t rowaddr = sV + (uint32_t)((kt * 16 + ln16) * A_ST) * 4;
#pragma unroll
            for (int nt = 0; nt < 8; ++nt) {
                uint32_t b[2];
                ldsm_x2t(b, rowaddr + nt * 16);
                mma_f16(Oa[nt], a, b);
            }
        }
    }
#undef A_ISSUE

    // ---- Final l reduction + writeback ----
    l_s[0] += __shfl_xor_sync(0xffffffffu, l_s[0], 1);
    l_s[0] += __shfl_xor_sync(0xffffffffu, l_s[0], 2);
    l_s[1] += __shfl_xor_sync(0xffffffffu, l_s[1], 1);
    l_s[1] += __shfl_xor_sync(0xffffffffu, l_s[1], 2);
    const float inv0 = 1.0f / l_s[0];
    const float inv1 = 1.0f / l_s[1];
    {
        size_t row = (size_t)(qrow0 + w16 + grp);
#pragma unroll
        for (int nt = 0; nt < 8; ++nt) {
            int col = col0 + nt * 8 + 2 * lq;
            __half2 lo = __floats2half2_rn(Oa[nt][0] * inv0, Oa[nt][1] * inv0);
            __half2 hi = __floats2half2_rn(Oa[nt][2] * inv1, Oa[nt][3] * inv1);
            *(uint32_t*)&O[row * DM + col]       = h2u(lo);
            *(uint32_t*)&O[(row + 8) * DM + col] = h2u(hi);
        }
    }
}

// ---------------------------------------------------------------------------
extern "C" void kernel_launch(void* const* d_in, const int* in_sizes, int n_in,
                              void* d_out, int out_size) {
    const float* x  = (const float*)d_in[0];
    const float* wq = (const float*)d_in[1];
    const float* wk = (const float*)d_in[2];
    const float* wv = (const float*)d_in[3];
    const float* wo = (const float*)d_in[4];
    float* out = (float*)d_out;

    __half *q, *k, *v, *ctx, *xh, *wqh, *wkh, *wvh, *woh;
    cudaGetSymbolAddress((void**)&q,   g_q);
    cudaGetSymbolAddress((void**)&k,   g_k);
    cudaGetSymbolAddress((void**)&v,   g_v);
    cudaGetSymbolAddress((void**)&ctx, g_ctx);
    cudaGetSymbolAddress((void**)&xh,  g_xh);
    cudaGetSymbolAddress((void**)&wqh, g_wqh);
    cudaGetSymbolAddress((void**)&wkh, g_wkh);
    cudaGetSymbolAddress((void**)&wvh, g_wvh);
    cudaGetSymbolAddress((void**)&woh, g_woh);

    cudaFuncSetAttribute(attn_f16, cudaFuncAttributeMaxDynamicSharedMemorySize,
                         A_SMEM);
    cudaFuncSetAttribute(gemm_f16<true>,
                         cudaFuncAttributeMaxDynamicSharedMemorySize, G_SMEM);
    cudaFuncSetAttribute(gemm_f16<false>,
                         cudaFuncAttributeMaxDynamicSharedMemorySize, G_SMEM);

    // 1) fp32 -> fp16 conversion of x + weights
    cvt_prep<<<dim3(1024, 1, 8), 256>>>(x, wq, wk, wv, wo);

    // 2) fused QKV projection
    dim3 qkv_grid(DM / 128, SEQ / 128, 3);
    gemm_f16<true><<<qkv_grid, 256, G_SMEM>>>(xh, wqh, wkh, wvh, q, k, v, QSCALE);

    // 3) attention
    attn_f16<<<dim3(SEQ / 128, NH), 256, A_SMEM>>>(q, k, v, ctx);

    // 4) output projection (fp32 out)
    dim3 wo_grid(DM / 128, SEQ / 128, 1);
    gemm_f16<false><<<wo_grid, 256, G_SMEM>>>(ctx, woh, woh, woh, out, out, out, 1.0f);
}

// round 12
// speedup vs baseline: 1.1698x; 1.0544x over previous
#include <cuda_runtime.h>
#include <cuda_fp16.h>
#include <cstdint>

static constexpr int SEQ = 4096;
static constexpr int DM  = 1024;
static constexpr int NH  = 16;
static constexpr int HD  = 64;

#define QSCALE 0.18033688011112042f  // 0.125 * log2(e)

// Scratch (allocation-free rule: device globals). All fp16.
__device__ __half g_q[SEQ * DM];
__device__ __half g_k[SEQ * DM];
__device__ __half g_v[SEQ * DM];
__device__ __half g_ctx[SEQ * DM];
__device__ __half g_xh[SEQ * DM];
__device__ __half g_wqh[DM * DM];
__device__ __half g_wkh[DM * DM];
__device__ __half g_wvh[DM * DM];
__device__ __half g_woh[DM * DM];

__device__ __forceinline__ float ex2f(float x) {
    float y;
    asm("ex2.approx.f32 %0, %1;" : "=f"(y) : "f"(x));
    return y;
}
__device__ __forceinline__ uint32_t h2u(__half2 h) { return *(uint32_t*)&h; }

__device__ __forceinline__ void mma_f16(float* d, const uint32_t* a, const uint32_t* b) {
    asm volatile(
        "mma.sync.aligned.m16n8k16.row.col.f32.f16.f16.f32 "
        "{%0,%1,%2,%3}, {%4,%5,%6,%7}, {%8,%9}, {%0,%1,%2,%3};"
        : "+f"(d[0]), "+f"(d[1]), "+f"(d[2]), "+f"(d[3])
        : "r"(a[0]), "r"(a[1]), "r"(a[2]), "r"(a[3]), "r"(b[0]), "r"(b[1]));
}

__device__ __forceinline__ uint32_t smem_u32(const void* p) {
    uint32_t a;
    asm("{ .reg .u64 t; cvta.to.shared.u64 t, %1; cvt.u32.u64 %0, t; }"
        : "=r"(a) : "l"(p));
    return a;
}

__device__ __forceinline__ void ldsm_x4(uint32_t* r, uint32_t addr) {
    asm volatile("ldmatrix.sync.aligned.m8n8.x4.shared.b16 {%0,%1,%2,%3}, [%4];"
                 : "=r"(r[0]), "=r"(r[1]), "=r"(r[2]), "=r"(r[3]) : "r"(addr));
}
__device__ __forceinline__ void ldsm_x4t(uint32_t* r, uint32_t addr) {
    asm volatile("ldmatrix.sync.aligned.m8n8.x4.trans.shared.b16 {%0,%1,%2,%3}, [%4];"
                 : "=r"(r[0]), "=r"(r[1]), "=r"(r[2]), "=r"(r[3]) : "r"(addr));
}

__device__ __forceinline__ void cp16(uint32_t dst, const void* src) {
    asm volatile("cp.async.cg.shared.global [%0], [%1], 16;" :: "r"(dst), "l"(src));
}
#define CP_COMMIT() asm volatile("cp.async.commit_group;" ::: "memory")
#define CP_WAIT0()  asm volatile("cp.async.wait_group 0;" ::: "memory")
#define CP_WAIT1()  asm volatile("cp.async.wait_group 1;" ::: "memory")
#define CP_WAIT2()  asm volatile("cp.async.wait_group 2;" ::: "memory")
#define CP_WAIT3()  asm volatile("cp.async.wait_group 3;" ::: "memory")

// ---------------------------------------------------------------------------
// Prep: fp32 -> fp16 (rn) for x and the four weights.
// ---------------------------------------------------------------------------
__global__ void __launch_bounds__(256) cvt_prep(const float* __restrict__ x,
                                                const float* __restrict__ wq,
                                                const float* __restrict__ wk,
                                                const float* __restrict__ wv,
                                                const float* __restrict__ wo) {
    const int z = blockIdx.z;
    const int idx = blockIdx.x * 256 + threadIdx.x;
    constexpr int MSEG = 1024 * 1024;
    const float* src;
    __half* dst;
    if (z < 4)       { src = x + (size_t)z * MSEG; dst = g_xh + (size_t)z * MSEG; }
    else if (z == 4) { src = wq; dst = g_wqh; }
    else if (z == 5) { src = wk; dst = g_wkh; }
    else if (z == 6) { src = wv; dst = g_wvh; }
    else             { src = wo; dst = g_woh; }
    float4 v = ((const float4*)src)[idx];
    ((uint2*)dst)[idx] = make_uint2(h2u(__floats2half2_rn(v.x, v.y)),
                                    h2u(__floats2half2_rn(v.z, v.w)));
}

// ---------------------------------------------------------------------------
// FP16 GEMM (NT): BM=BN=128, BK=32, 8 warps 2(M)x4(N), warp 64x32.
// 5-stage cp.async pipeline, one barrier/iter. B fragments via paired ldsm_x4
// (one ldsm feeds two n-tiles). Row stride 20 words: conflict-free.
// ---------------------------------------------------------------------------
static constexpr int G_ST    = 20;
static constexpr int G_STA   = 128 * G_ST;
static constexpr int G_STG   = 2 * G_STA;
static constexpr int G_NSTG  = 5;
static constexpr int G_SMEM  = G_NSTG * G_STG * 4;   // 102400 bytes
static constexpr int G_NIT   = DM / 32;              // 32

template <bool CVT_OUT>
__global__ void __launch_bounds__(256, 2)
gemm_f16(const __half* __restrict__ A,
         const __half* __restrict__ B0, const __half* __restrict__ B1,
         const __half* __restrict__ B2,
         void* __restrict__ C0, void* __restrict__ C1, void* __restrict__ C2,
         float scale0) {
    extern __shared__ uint32_t smg[];

    const __half* B = (blockIdx.z == 0) ? B0 : (blockIdx.z == 1 ? B1 : B2);
    void*         C = (blockIdx.z == 0) ? C0 : (blockIdx.z == 1 ? C1 : C2);
    const float oscale = (blockIdx.z == 0) ? scale0 : 1.0f;

    const int tid  = threadIdx.x;
    const int warp = tid >> 5;
    const int lane = tid & 31;
    const int grp  = lane >> 2;
    const int lq   = lane & 3;
    const int ln16 = lane & 15;
    const int hi16 = lane >> 4;
    const int wm0  = (warp & 1) * 64;
    const int wn0  = (warp >> 1) * 32;

    // paired-x4 B lane map: rows +8 for upper half-warp, k-half from bit3
    const int brow_off = (lane & 7) + ((lane >> 4) << 3);
    const int bk_off   = ((lane >> 3) & 1) * 4;

    const int bm = blockIdx.y * 128;
    const int bn = blockIdx.x * 128;

    const __half* Ag = A + (size_t)(bm + (tid >> 1)) * DM + (tid & 1) * 16;
    const __half* Bg = B + (size_t)(bn + (tid >> 1)) * DM + (tid & 1) * 16;
    const uint32_t smb = smem_u32(smg);
    const uint32_t a_sm = smb + (uint32_t)((tid >> 1) * G_ST + (tid & 1) * 8) * 4;
    const uint32_t b_sm = a_sm + (uint32_t)G_STA * 4;

#define G_ISSUE(it, stg)                                                      \
    do {                                                                      \
        const __half* ap = Ag + (size_t)(it) * 32;                            \
        const __half* bp = Bg + (size_t)(it) * 32;                            \
        uint32_t so = (uint32_t)(stg) * G_STG * 4;                            \
        cp16(a_sm + so, ap); cp16(a_sm + so + 16, ap + 8);                    \
        cp16(b_sm + so, bp); cp16(b_sm + so + 16, bp + 8);                    \
        CP_COMMIT();                                                          \
    } while (0)

    G_ISSUE(0, 0);
    G_ISSUE(1, 1);
    G_ISSUE(2, 2);
    G_ISSUE(3, 3);

    float acc[4][4][4] = {};

#pragma unroll 1
    for (int i = 0; i < G_NIT; ++i) {
        {
            const int rem = G_NIT - 1 - i;
            if (rem >= 3)      { CP_WAIT3(); }
            else if (rem == 2) { CP_WAIT2(); }
            else if (rem == 1) { CP_WAIT1(); }
            else               { CP_WAIT0(); }
        }
        __syncthreads();
        if (i + 4 < G_NIT) G_ISSUE(i + 4, (i + 4) % G_NSTG);

        const uint32_t sA = smb + (uint32_t)(i % G_NSTG) * G_STG * 4;
        const uint32_t sB = sA + (uint32_t)G_STA * 4;

#pragma unroll
        for (int s = 0; s < 2; ++s) {
            uint32_t afr[4][4];
#pragma unroll
            for (int im = 0; im < 4; ++im)
                ldsm_x4(afr[im],
                        sA + (uint32_t)((wm0 + im * 16 + ln16) * G_ST + s * 8 + hi16 * 4) * 4);
#pragma unroll
            for (int inp = 0; inp < 2; ++inp) {
                uint32_t bf[4];
                ldsm_x4(bf, sB + (uint32_t)((wn0 + inp * 16 + brow_off) * G_ST
                                            + s * 8 + bk_off) * 4);
#pragma unroll
                for (int im = 0; im < 4; ++im) {
                    mma_f16(acc[im][2 * inp],     afr[im], bf);
                    mma_f16(acc[im][2 * inp + 1], afr[im], bf + 2);
                }
            }
        }
    }
#undef G_ISSUE

#pragma unroll
    for (int im = 0; im < 4; ++im) {
#pragma unroll
        for (int in = 0; in < 4; ++in) {
            size_t row0 = (size_t)(bm + wm0 + im * 16 + grp);
            int col = bn + wn0 + in * 8 + 2 * lq;
            if (CVT_OUT) {
                __half* Ch = (__half*)C;
                __half2 lo = __floats2half2_rn(acc[im][in][0] * oscale,
                                               acc[im][in][1] * oscale);
                __half2 hi = __floats2half2_rn(acc[im][in][2] * oscale,
                                               acc[im][in][3] * oscale);
                *(uint32_t*)&Ch[row0 * DM + col]       = h2u(lo);
                *(uint32_t*)&Ch[(row0 + 8) * DM + col] = h2u(hi);
            } else {
                float* Cf = (float*)C;
                *(float2*)&Cf[row0 * DM + col] =
                    make_float2(acc[im][in][0], acc[im][in][1]);
                *(float2*)&Cf[(row0 + 8) * DM + col] =
                    make_float2(acc[im][in][2], acc[im][in][3]);
            }
        }
    }
}

// ---------------------------------------------------------------------------
// Flash attention, fp16 MMA m16n8k16, kv-tile 64, 3-stage cp.async K/V.
// Q fragments hoisted to registers (loaded once). K via paired ldsm_x4,
// V via paired ldsm_x4.trans (one ldsm = two n-tiles).
// ---------------------------------------------------------------------------
static constexpr int A_ST   = 36;
static constexpr int A_QW   = 128 * A_ST;
static constexpr int A_KVW  = 64 * A_ST;
static constexpr int A_STG  = 2 * A_KVW;
static constexpr int A_SMEM = (A_QW + 3 * A_STG) * 4;     // 73728 bytes

__global__ void __launch_bounds__(256, 2) attn_f16(const __half* __restrict__ Q,
                                                   const __half* __restrict__ K,
                                                   const __half* __restrict__ V,
                                                   __half* __restrict__ O) {
    extern __shared__ uint32_t sm[];

    const int tid  = threadIdx.x;
    const int lane = tid & 31;
    const int grp  = lane >> 2;
    const int lq   = lane & 3;
    const int ln16 = lane & 15;
    const int hi16 = lane >> 4;
    const int head = blockIdx.y;
    const int qt   = (int)gridDim.x - 1 - (int)blockIdx.x;  // long CTAs first
    const int qrow0 = qt * 128;
    const int col0  = head * HD;
    const int w16   = (tid >> 5) * 16;

    // paired-x4 lane maps
    const int brow_off = (lane & 7) + ((lane >> 4) << 3);      // K (non-trans)
    const int bk_off   = ((lane >> 3) & 1) * 4;
    const int vrow_off = (lane & 7) + (((lane >> 3) & 1) << 3);  // V (trans)
    const int vcol_sel = lane >> 4;

    const uint32_t smb = smem_u32(sm);

    const int krow = tid >> 2;
    const int kch  = (tid & 3) * 16;
    const __half* Ksrc = K + (size_t)krow * DM + col0 + kch;
    const __half* Vsrc = V + (size_t)krow * DM + col0 + kch;
    const uint32_t ksd = smb + (uint32_t)(A_QW + krow * A_ST + (tid & 3) * 8) * 4;
    const uint32_t vsd = ksd + (uint32_t)A_KVW * 4;

    const int nkb = 2 * qt + 2;

#define A_ISSUE(kb_, stg)                                                     \
    do {                                                                      \
        const __half* Kp = Ksrc + (size_t)(kb_) * 64 * DM;                    \
        const __half* Vp = Vsrc + (size_t)(kb_) * 64 * DM;                    \
        const uint32_t so = (uint32_t)((stg) * A_STG) * 4;                    \
        cp16(ksd + so, Kp); cp16(ksd + so + 16, Kp + 8);                      \
        cp16(vsd + so, Vp); cp16(vsd + so + 16, Vp + 8);                      \
        CP_COMMIT();                                                          \
    } while (0)

    // ---- Prologue: Q + K/V(0) group 0; K/V(1) group 1 ----
    {
        int qrow = tid >> 1;
        const __half* qs = Q + (size_t)(qrow0 + qrow) * DM + col0 + (tid & 1) * 32;
        uint32_t qd = smb + (uint32_t)(qrow * A_ST + (tid & 1) * 16) * 4;
#pragma unroll
        for (int p = 0; p < 4; ++p) cp16(qd + p * 16, qs + p * 8);
    }
    A_ISSUE(0, 0);
    A_ISSUE(1, 1);

    // ---- Hoist Q fragments to registers (group 0 complete first) ----
    uint32_t qfr[4][4];
    CP_WAIT1();
    __syncthreads();
#pragma unroll
    for (int kt = 0; kt < 4; ++kt)
        ldsm_x4(qfr[kt], smb + (uint32_t)((w16 + ln16) * A_ST + kt * 8 + hi16 * 4) * 4);

    float Oa[8][4];
    float l_s[2] = {0.0f, 0.0f};
#pragma unroll
    for (int nt = 0; nt < 8; ++nt)
#pragma unroll
        for (int c = 0; c < 4; ++c) Oa[nt][c] = 0.0f;

    for (int kb = 0; kb < nkb; ++kb) {
        if (kb < nkb - 1) { CP_WAIT1(); } else { CP_WAIT0(); }
        __syncthreads();
        if (kb + 2 < nkb) A_ISSUE(kb + 2, (kb + 2) % 3);

        const uint32_t sK = smb + (uint32_t)(A_QW + (kb % 3) * A_STG) * 4;
        const uint32_t sV = sK + (uint32_t)A_KVW * 4;

        // ---- S = Q K^T : paired-n K loads ----
        float S[8][4];
#pragma unroll
        for (int nt = 0; nt < 8; ++nt)
#pragma unroll
            for (int c = 0; c < 4; ++c) S[nt][c] = 0.0f;

#pragma unroll
        for (int kt = 0; kt < 4; ++kt) {
#pragma unroll
            for (int ntp = 0; ntp < 4; ++ntp) {
                uint32_t bk[4];
                ldsm_x4(bk, sK + (uint32_t)((ntp * 16 + brow_off) * A_ST
                                            + kt * 8 + bk_off) * 4);
                mma_f16(S[2 * ntp],     qfr[kt], bk);
                mma_f16(S[2 * ntp + 1], qfr[kt], bk + 2);
            }
        }

        // ---- Causal mask ----
        if (kb >= 2 * qt) {
#pragma unroll
            for (int nt = 0; nt < 8; ++nt)
#pragma unroll
                for (int c = 0; c < 4; ++c) {
                    int qi = qrow0 + w16 + grp + ((c >> 1) << 3);
                    int kj = kb * 64 + nt * 8 + 2 * lq + (c & 1);
                    if (kj > qi) S[nt][c] = -10000.0f;
                }
        }

        // ---- p = 2^s; accumulate l ----
#pragma unroll
        for (int nt = 0; nt < 8; ++nt) {
            float p0 = ex2f(S[nt][0]);
            float p1 = ex2f(S[nt][1]);
            float p2 = ex2f(S[nt][2]);
            float p3 = ex2f(S[nt][3]);
            l_s[0] += p0 + p1;
            l_s[1] += p2 + p3;
            S[nt][0] = p0; S[nt][1] = p1; S[nt][2] = p2; S[nt][3] = p3;
        }

        // ---- O += P V : paired-n trans V loads ----
#pragma unroll
        for (int kt = 0; kt < 4; ++kt) {
            uint32_t a[4];
            a[0] = h2u(__floats2half2_rn(S[2 * kt][0],     S[2 * kt][1]));
            a[1] = h2u(__floats2half2_rn(S[2 * kt][2],     S[2 * kt][3]));
            a[2] = h2u(__floats2half2_rn(S[2 * kt + 1][0], S[2 * kt + 1][1]));
            a[3] = h2u(__floats2half2_rn(S[2 * kt + 1][2], S[2 * kt + 1][3]));
            const uint32_t rowbase = sV + (uint32_t)((kt * 16 + vrow_off) * A_ST) * 4;
#pragma unroll
            for (int ntp = 0; ntp < 4; ++ntp) {
                uint32_t bv[4];
                ldsm_x4t(bv, rowbase + (uint32_t)(ntp * 2 + vcol_sel) * 16);
                mma_f16(Oa[2 * ntp],     a, bv);
                mma_f16(Oa[2 * ntp + 1], a, bv + 2);
            }
        }
    }
#undef A_ISSUE

    // ---- Final l reduction + writeback ----
    l_s[0] += __shfl_xor_sync(0xffffffffu, l_s[0], 1);
    l_s[0] += __shfl_xor_sync(0xffffffffu, l_s[0], 2);
    l_s[1] += __shfl_xor_sync(0xffffffffu, l_s[1], 1);
    l_s[1] += __shfl_xor_sync(0xffffffffu, l_s[1], 2);
    const float inv0 = 1.0f / l_s[0];
    const float inv1 = 1.0f / l_s[1];
    {
        size_t row = (size_t)(qrow0 + w16 + grp);
#pragma unroll
        for (int nt = 0; nt < 8; ++nt) {
            int col = col0 + nt * 8 + 2 * lq;
            __half2 lo = __floats2half2_rn(Oa[nt][0] * inv0, Oa[nt][1] * inv0);
            __half2 hi = __floats2half2_rn(Oa[nt][2] * inv1, Oa[nt][3] * inv1);
            *(uint32_t*)&O[row * DM + col]       = h2u(lo);
            *(uint32_t*)&O[(row + 8) * DM + col] = h2u(hi);
        }
    }
}

// ---------------------------------------------------------------------------
extern "C" void kernel_launch(void* const* d_in, const int* in_sizes, int n_in,
                              void* d_out, int out_size) {
    const float* x  = (const float*)d_in[0];
    const float* wq = (const float*)d_in[1];
    const float* wk = (const float*)d_in[2];
    const float* wv = (const float*)d_in[3];
    const float* wo = (const float*)d_in[4];
    float* out = (float*)d_out;

    __half *q, *k, *v, *ctx, *xh, *wqh, *wkh, *wvh, *woh;
    cudaGetSymbolAddress((void**)&q,   g_q);
    cudaGetSymbolAddress((void**)&k,   g_k);
    cudaGetSymbolAddress((void**)&v,   g_v);
    cudaGetSymbolAddress((void**)&ctx, g_ctx);
    cudaGetSymbolAddress((void**)&xh,  g_xh);
    cudaGetSymbolAddress((void**)&wqh, g_wqh);
    cudaGetSymbolAddress((void**)&wkh, g_wkh);
    cudaGetSymbolAddress((void**)&wvh, g_wvh);
    cudaGetSymbolAddress((void**)&woh, g_woh);

    cudaFuncSetAttribute(attn_f16, cudaFuncAttributeMaxDynamicSharedMemorySize,
                         A_SMEM);
    cudaFuncSetAttribute(gemm_f16<true>,
                         cudaFuncAttributeMaxDynamicSharedMemorySize, G_SMEM);
    cudaFuncSetAttribute(gemm_f16<false>,
                         cudaFuncAttributeMaxDynamicSharedMemorySize, G_SMEM);

    // 1) fp32 -> fp16 conversion of x + weights
    cvt_prep<<<dim3(1024, 1, 8), 256>>>(x, wq, wk, wv, wo);

    // 2) fused QKV projection
    dim3 qkv_grid(DM / 128, SEQ / 128, 3);
    gemm_f16<true><<<qkv_grid, 256, G_SMEM>>>(xh, wqh, wkh, wvh, q, k, v, QSCALE);

    // 3) attention
    attn_f16<<<dim3(SEQ / 128, NH), 256, A_SMEM>>>(q, k, v, ctx);

    // 4) output projection (fp32 out)
    dim3 wo_grid(DM / 128, SEQ / 128, 1);
    gemm_f16<false><<<wo_grid, 256, G_SMEM>>>(ctx, woh, woh, woh, out, out, out, 1.0f);
}

// round 13
// speedup vs baseline: 1.1768x; 1.0060x over previous
#include <cuda_runtime.h>
#include <cuda_fp16.h>
#include <cstdint>

static constexpr int SEQ = 4096;
static constexpr int DM  = 1024;
static constexpr int NH  = 16;
static constexpr int HD  = 64;

#define QSCALE 0.18033688011112042f  // 0.125 * log2(e)

// Scratch (allocation-free rule: device globals). All fp16.
__device__ __half g_q[SEQ * DM];
__device__ __half g_k[SEQ * DM];
__device__ __half g_v[SEQ * DM];
__device__ __half g_ctx[SEQ * DM];
__device__ __half g_xh[SEQ * DM];
__device__ __half g_wqh[DM * DM];
__device__ __half g_wkh[DM * DM];
__device__ __half g_wvh[DM * DM];
__device__ __half g_woh[DM * DM];

__device__ __forceinline__ uint32_t h2u(__half2 h) { return *(uint32_t*)&h; }

__device__ __forceinline__ void mma_f16(float* d, const uint32_t* a, const uint32_t* b) {
    asm volatile(
        "mma.sync.aligned.m16n8k16.row.col.f32.f16.f16.f32 "
        "{%0,%1,%2,%3}, {%4,%5,%6,%7}, {%8,%9}, {%0,%1,%2,%3};"
        : "+f"(d[0]), "+f"(d[1]), "+f"(d[2]), "+f"(d[3])
        : "r"(a[0]), "r"(a[1]), "r"(a[2]), "r"(a[3]), "r"(b[0]), "r"(b[1]));
}

__device__ __forceinline__ uint32_t smem_u32(const void* p) {
    uint32_t a;
    asm("{ .reg .u64 t; cvta.to.shared.u64 t, %1; cvt.u32.u64 %0, t; }"
        : "=r"(a) : "l"(p));
    return a;
}

__device__ __forceinline__ void ldsm_x4(uint32_t* r, uint32_t addr) {
    asm volatile("ldmatrix.sync.aligned.m8n8.x4.shared.b16 {%0,%1,%2,%3}, [%4];"
                 : "=r"(r[0]), "=r"(r[1]), "=r"(r[2]), "=r"(r[3]) : "r"(addr));
}
__device__ __forceinline__ void ldsm_x4t(uint32_t* r, uint32_t addr) {
    asm volatile("ldmatrix.sync.aligned.m8n8.x4.trans.shared.b16 {%0,%1,%2,%3}, [%4];"
                 : "=r"(r[0]), "=r"(r[1]), "=r"(r[2]), "=r"(r[3]) : "r"(addr));
}

__device__ __forceinline__ void cp16(uint32_t dst, const void* src) {
    asm volatile("cp.async.cg.shared.global [%0], [%1], 16;" :: "r"(dst), "l"(src));
}
#define CP_COMMIT() asm volatile("cp.async.commit_group;" ::: "memory")
#define CP_WAIT0()  asm volatile("cp.async.wait_group 0;" ::: "memory")
#define CP_WAIT1()  asm volatile("cp.async.wait_group 1;" ::: "memory")
#define CP_WAIT2()  asm volatile("cp.async.wait_group 2;" ::: "memory")
#define CP_WAIT3()  asm volatile("cp.async.wait_group 3;" ::: "memory")

// ---------------------------------------------------------------------------
// Prep: fp32 -> fp16 (rn) for x and the four weights.
// ---------------------------------------------------------------------------
__global__ void __launch_bounds__(256) cvt_prep(const float* __restrict__ x,
                                                const float* __restrict__ wq,
                                                const float* __restrict__ wk,
                                                const float* __restrict__ wv,
                                                const float* __restrict__ wo) {
    const int z = blockIdx.z;
    const int idx = blockIdx.x * 256 + threadIdx.x;
    constexpr int MSEG = 1024 * 1024;
    const float* src;
    __half* dst;
    if (z < 4)       { src = x + (size_t)z * MSEG; dst = g_xh + (size_t)z * MSEG; }
    else if (z == 4) { src = wq; dst = g_wqh; }
    else if (z == 5) { src = wk; dst = g_wkh; }
    else if (z == 6) { src = wv; dst = g_wvh; }
    else             { src = wo; dst = g_woh; }
    float4 v = ((const float4*)src)[idx];
    ((uint2*)dst)[idx] = make_uint2(h2u(__floats2half2_rn(v.x, v.y)),
                                    h2u(__floats2half2_rn(v.z, v.w)));
}

// ---------------------------------------------------------------------------
// FP16 GEMM (NT): BM=BN=128, BK=32, 8 warps 2(M)x4(N), warp 64x32.
// 5-stage cp.async pipeline, one barrier/iter. B fragments via paired ldsm_x4.
// (unchanged from round 12 passing version)
// ---------------------------------------------------------------------------
static constexpr int G_ST    = 20;
static constexpr int G_STA   = 128 * G_ST;
static constexpr int G_STG   = 2 * G_STA;
static constexpr int G_NSTG  = 5;
static constexpr int G_SMEM  = G_NSTG * G_STG * 4;   // 102400 bytes
static constexpr int G_NIT   = DM / 32;              // 32

template <bool CVT_OUT>
__global__ void __launch_bounds__(256, 2)
gemm_f16(const __half* __restrict__ A,
         const __half* __restrict__ B0, const __half* __restrict__ B1,
         const __half* __restrict__ B2,
         void* __restrict__ C0, void* __restrict__ C1, void* __restrict__ C2,
         float scale0) {
    extern __shared__ uint32_t smg[];

    const __half* B = (blockIdx.z == 0) ? B0 : (blockIdx.z == 1 ? B1 : B2);
    void*         C = (blockIdx.z == 0) ? C0 : (blockIdx.z == 1 ? C1 : C2);
    const float oscale = (blockIdx.z == 0) ? scale0 : 1.0f;

    const int tid  = threadIdx.x;
    const int warp = tid >> 5;
    const int lane = tid & 31;
    const int grp  = lane >> 2;
    const int lq   = lane & 3;
    const int ln16 = lane & 15;
    const int hi16 = lane >> 4;
    const int wm0  = (warp & 1) * 64;
    const int wn0  = (warp >> 1) * 32;

    const int brow_off = (lane & 7) + ((lane >> 4) << 3);
    const int bk_off   = ((lane >> 3) & 1) * 4;

    const int bm = blockIdx.y * 128;
    const int bn = blockIdx.x * 128;

    const __half* Ag = A + (size_t)(bm + (tid >> 1)) * DM + (tid & 1) * 16;
    const __half* Bg = B + (size_t)(bn + (tid >> 1)) * DM + (tid & 1) * 16;
    const uint32_t smb = smem_u32(smg);
    const uint32_t a_sm = smb + (uint32_t)((tid >> 1) * G_ST + (tid & 1) * 8) * 4;
    const uint32_t b_sm = a_sm + (uint32_t)G_STA * 4;

#define G_ISSUE(it, stg)                                                      \
    do {                                                                      \
        const __half* ap = Ag + (size_t)(it) * 32;                            \
        const __half* bp = Bg + (size_t)(it) * 32;                            \
        uint32_t so = (uint32_t)(stg) * G_STG * 4;                            \
        cp16(a_sm + so, ap); cp16(a_sm + so + 16, ap + 8);                    \
        cp16(b_sm + so, bp); cp16(b_sm + so + 16, bp + 8);                    \
        CP_COMMIT();                                                          \
    } while (0)

    G_ISSUE(0, 0);
    G_ISSUE(1, 1);
    G_ISSUE(2, 2);
    G_ISSUE(3, 3);

    float acc[4][4][4] = {};

#pragma unroll 1
    for (int i = 0; i < G_NIT; ++i) {
        {
            const int rem = G_NIT - 1 - i;
            if (rem >= 3)      { CP_WAIT3(); }
            else if (rem == 2) { CP_WAIT2(); }
            else if (rem == 1) { CP_WAIT1(); }
            else               { CP_WAIT0(); }
        }
        __syncthreads();
        if (i + 4 < G_NIT) G_ISSUE(i + 4, (i + 4) % G_NSTG);

        const uint32_t sA = smb + (uint32_t)(i % G_NSTG) * G_STG * 4;
        const uint32_t sB = sA + (uint32_t)G_STA * 4;

#pragma unroll
        for (int s = 0; s < 2; ++s) {
            uint32_t afr[4][4];
#pragma unroll
            for (int im = 0; im < 4; ++im)
                ldsm_x4(afr[im],
                        sA + (uint32_t)((wm0 + im * 16 + ln16) * G_ST + s * 8 + hi16 * 4) * 4);
#pragma unroll
            for (int inp = 0; inp < 2; ++inp) {
                uint32_t bf[4];
                ldsm_x4(bf, sB + (uint32_t)((wn0 + inp * 16 + brow_off) * G_ST
                                            + s * 8 + bk_off) * 4);
#pragma unroll
                for (int im = 0; im < 4; ++im) {
                    mma_f16(acc[im][2 * inp],     afr[im], bf);
                    mma_f16(acc[im][2 * inp + 1], afr[im], bf + 2);
                }
            }
        }
    }
#undef G_ISSUE

#pragma unroll
    for (int im = 0; im < 4; ++im) {
#pragma unroll
        for (int in = 0; in < 4; ++in) {
            size_t row0 = (size_t)(bm + wm0 + im * 16 + grp);
            int col = bn + wn0 + in * 8 + 2 * lq;
            if (CVT_OUT) {
                __half* Ch = (__half*)C;
                __half2 lo = __floats2half2_rn(acc[im][in][0] * oscale,
                                               acc[im][in][1] * oscale);
                __half2 hi = __floats2half2_rn(acc[im][in][2] * oscale,
                                               acc[im][in][3] * oscale);
                *(uint32_t*)&Ch[row0 * DM + col]       = h2u(lo);
                *(uint32_t*)&Ch[(row0 + 8) * DM + col] = h2u(hi);
            } else {
                float* Cf = (float*)C;
                *(float2*)&Cf[row0 * DM + col] =
                    make_float2(acc[im][in][0], acc[im][in][1]);
                *(float2*)&Cf[(row0 + 8) * DM + col] =
                    make_float2(acc[im][in][2], acc[im][in][3]);
            }
        }
    }
}

// ---------------------------------------------------------------------------
// Flash attention, fp16 MMA m16n8k16, kv-tile 64, 3-stage cp.async K/V.
// Q fragments in registers. K paired ldsm_x4, V paired ldsm_x4.trans.
// NEW: softmax via ex2.approx.f16x2 (halves MUFU load); the f16x2 outputs
// ARE the PV A-fragments (no pack cvts); l from HADD2 pair sums.
// ---------------------------------------------------------------------------
static constexpr int A_ST   = 36;
static constexpr int A_QW   = 128 * A_ST;
static constexpr int A_KVW  = 64 * A_ST;
static constexpr int A_STG  = 2 * A_KVW;
static constexpr int A_SMEM = (A_QW + 3 * A_STG) * 4;     // 73728 bytes

__global__ void __launch_bounds__(256, 2) attn_f16(const __half* __restrict__ Q,
                                                   const __half* __restrict__ K,
                                                   const __half* __restrict__ V,
                                                   __half* __restrict__ O) {
    extern __shared__ uint32_t sm[];

    const int tid  = threadIdx.x;
    const int lane = tid & 31;
    const int grp  = lane >> 2;
    const int lq   = lane & 3;
    const int ln16 = lane & 15;
    const int hi16 = lane >> 4;
    const int head = blockIdx.y;
    const int qt   = (int)gridDim.x - 1 - (int)blockIdx.x;  // long CTAs first
    const int qrow0 = qt * 128;
    const int col0  = head * HD;
    const int w16   = (tid >> 5) * 16;

    const int brow_off = (lane & 7) + ((lane >> 4) << 3);        // K (non-trans)
    const int bk_off   = ((lane >> 3) & 1) * 4;
    const int vrow_off = (lane & 7) + (((lane >> 3) & 1) << 3);  // V (trans)
    const int vcol_sel = lane >> 4;

    const uint32_t smb = smem_u32(sm);

    const int krow = tid >> 2;
    const int kch  = (tid & 3) * 16;
    const __half* Ksrc = K + (size_t)krow * DM + col0 + kch;
    const __half* Vsrc = V + (size_t)krow * DM + col0 + kch;
    const uint32_t ksd = smb + (uint32_t)(A_QW + krow * A_ST + (tid & 3) * 8) * 4;
    const uint32_t vsd = ksd + (uint32_t)A_KVW * 4;

    const int nkb = 2 * qt + 2;

#define A_ISSUE(kb_, stg)                                                     \
    do {                                                                      \
        const __half* Kp = Ksrc + (size_t)(kb_) * 64 * DM;                    \
        const __half* Vp = Vsrc + (size_t)(kb_) * 64 * DM;                    \
        const uint32_t so = (uint32_t)((stg) * A_STG) * 4;                    \
        cp16(ksd + so, Kp); cp16(ksd + so + 16, Kp + 8);                      \
        cp16(vsd + so, Vp); cp16(vsd + so + 16, Vp + 8);                      \
        CP_COMMIT();                                                          \
    } while (0)

    // ---- Prologue: Q + K/V(0) group 0; K/V(1) group 1 ----
    {
        int qrow = tid >> 1;
        const __half* qs = Q + (size_t)(qrow0 + qrow) * DM + col0 + (tid & 1) * 32;
        uint32_t qd = smb + (uint32_t)(qrow * A_ST + (tid & 1) * 16) * 4;
#pragma unroll
        for (int p = 0; p < 4; ++p) cp16(qd + p * 16, qs + p * 8);
    }
    A_ISSUE(0, 0);
    A_ISSUE(1, 1);

    // ---- Hoist Q fragments to registers ----
    uint32_t qfr[4][4];
    CP_WAIT1();
    __syncthreads();
#pragma unroll
    for (int kt = 0; kt < 4; ++kt)
        ldsm_x4(qfr[kt], smb + (uint32_t)((w16 + ln16) * A_ST + kt * 8 + hi16 * 4) * 4);

    float Oa[8][4];
    float l_s[2] = {0.0f, 0.0f};
#pragma unroll
    for (int nt = 0; nt < 8; ++nt)
#pragma unroll
        for (int c = 0; c < 4; ++c) Oa[nt][c] = 0.0f;

    for (int kb = 0; kb < nkb; ++kb) {
        if (kb < nkb - 1) { CP_WAIT1(); } else { CP_WAIT0(); }
        __syncthreads();
        if (kb + 2 < nkb) A_ISSUE(kb + 2, (kb + 2) % 3);

        const uint32_t sK = smb + (uint32_t)(A_QW + (kb % 3) * A_STG) * 4;
        const uint32_t sV = sK + (uint32_t)A_KVW * 4;

        // ---- S = Q K^T : paired-n K loads ----
        float S[8][4];
#pragma unroll
        for (int nt = 0; nt < 8; ++nt)
#pragma unroll
            for (int c = 0; c < 4; ++c) S[nt][c] = 0.0f;

#pragma unroll
        for (int kt = 0; kt < 4; ++kt) {
#pragma unroll
            for (int ntp = 0; ntp < 4; ++ntp) {
                uint32_t bk[4];
                ldsm_x4(bk, sK + (uint32_t)((ntp * 16 + brow_off) * A_ST
                                            + kt * 8 + bk_off) * 4);
                mma_f16(S[2 * ntp],     qfr[kt], bk);
                mma_f16(S[2 * ntp + 1], qfr[kt], bk + 2);
            }
        }

        // ---- Causal mask ----
        if (kb >= 2 * qt) {
#pragma unroll
            for (int nt = 0; nt < 8; ++nt)
#pragma unroll
                for (int c = 0; c < 4; ++c) {
                    int qi = qrow0 + w16 + grp + ((c >> 1) << 3);
                    int kj = kb * 64 + nt * 8 + 2 * lq + (c & 1);
                    if (kj > qi) S[nt][c] = -10000.0f;
                }
        }

        // ---- p = 2^s via ex2.approx.f16x2; l from HADD2 pair sums ----
        // P[nt][0] = {lo=p(S0), hi=p(S1)}  == PV A-fragment layout directly.
        uint32_t P[8][2];
#pragma unroll
        for (int nt = 0; nt < 8; ++nt) {
            uint32_t slo, shi;
            asm("cvt.rn.f16x2.f32 %0, %1, %2;"
                : "=r"(slo) : "f"(S[nt][1]), "f"(S[nt][0]));
            asm("cvt.rn.f16x2.f32 %0, %1, %2;"
                : "=r"(shi) : "f"(S[nt][3]), "f"(S[nt][2]));
            asm("ex2.approx.f16x2 %0, %1;" : "=r"(P[nt][0]) : "r"(slo));
            asm("ex2.approx.f16x2 %0, %1;" : "=r"(P[nt][1]) : "r"(shi));
        }
#pragma unroll
        for (int nt = 0; nt < 8; ++nt) {
            __half2 plo = *(__half2*)&P[nt][0];
            __half2 phi = *(__half2*)&P[nt][1];
            l_s[0] += __half2float(__hadd(__low2half(plo), __high2half(plo)));
            l_s[1] += __half2float(__hadd(__low2half(phi), __high2half(phi)));
        }

        // ---- O += P V : paired-n trans V loads; A-frags are P directly ----
#pragma unroll
        for (int kt = 0; kt < 4; ++kt) {
            uint32_t a[4];
            a[0] = P[2 * kt][0];
            a[1] = P[2 * kt][1];
            a[2] = P[2 * kt + 1][0];
            a[3] = P[2 * kt + 1][1];
            const uint32_t rowbase = sV + (uint32_t)((kt * 16 + vrow_off) * A_ST) * 4;
#pragma unroll
            for (int ntp = 0; ntp < 4; ++ntp) {
                uint32_t bv[4];
                ldsm_x4t(bv, rowbase + (uint32_t)(ntp * 2 + vcol_sel) * 16);
                mma_f16(Oa[2 * ntp],     a, bv);
                mma_f16(Oa[2 * ntp + 1], a, bv + 2);
            }
        }
    }
#undef A_ISSUE

    // ---- Final l reduction + writeback ----
    l_s[0] += __shfl_xor_sync(0xffffffffu, l_s[0], 1);
    l_s[0] += __shfl_xor_sync(0xffffffffu, l_s[0], 2);
    l_s[1] += __shfl_xor_sync(0xffffffffu, l_s[1], 1);
    l_s[1] += __shfl_xor_sync(0xffffffffu, l_s[1], 2);
    const float inv0 = 1.0f / l_s[0];
    const float inv1 = 1.0f / l_s[1];
    {
        size_t row = (size_t)(qrow0 + w16 + grp);
#pragma unroll
        for (int nt = 0; nt < 8; ++nt) {
            int col = col0 + nt * 8 + 2 * lq;
            __half2 lo = __floats2half2_rn(Oa[nt][0] * inv0, Oa[nt][1] * inv0);
            __half2 hi = __floats2half2_rn(Oa[nt][2] * inv1, Oa[nt][3] * inv1);
            *(uint32_t*)&O[row * DM + col]       = h2u(lo);
            *(uint32_t*)&O[(row + 8) * DM + col] = h2u(hi);
        }
    }
}

// ---------------------------------------------------------------------------
extern "C" void kernel_launch(void* const* d_in, const int* in_sizes, int n_in,
                              void* d_out, int out_size) {
    const float* x  = (const float*)d_in[0];
    const float* wq = (const float*)d_in[1];
    const float* wk = (const float*)d_in[2];
    const float* wv = (const float*)d_in[3];
    const float* wo = (const float*)d_in[4];
    float* out = (float*)d_out;

    __half *q, *k, *v, *ctx, *xh, *wqh, *wkh, *wvh, *woh;
    cudaGetSymbolAddress((void**)&q,   g_q);
    cudaGetSymbolAddress((void**)&k,   g_k);
    cudaGetSymbolAddress((void**)&v,   g_v);
    cudaGetSymbolAddress((void**)&ctx, g_ctx);
    cudaGetSymbolAddress((void**)&xh,  g_xh);
    cudaGetSymbolAddress((void**)&wqh, g_wqh);
    cudaGetSymbolAddress((void**)&wkh, g_wkh);
    cudaGetSymbolAddress((void**)&wvh, g_wvh);
    cudaGetSymbolAddress((void**)&woh, g_woh);

    cudaFuncSetAttribute(attn_f16, cudaFuncAttributeMaxDynamicSharedMemorySize,
                         A_SMEM);
    cudaFuncSetAttribute(gemm_f16<true>,
                         cudaFuncAttributeMaxDynamicSharedMemorySize, G_SMEM);
    cudaFuncSetAttribute(gemm_f16<false>,
                         cudaFuncAttributeMaxDynamicSharedMemorySize, G_SMEM);

    // 1) fp32 -> fp16 conversion of x + weights
    cvt_prep<<<dim3(1024, 1, 8), 256>>>(x, wq, wk, wv, wo);

    // 2) fused QKV projection
    dim3 qkv_grid(DM / 128, SEQ / 128, 3);
    gemm_f16<true><<<qkv_grid, 256, G_SMEM>>>(xh, wqh, wkh, wvh, q, k, v, QSCALE);

    // 3) attention
    attn_f16<<<dim3(SEQ / 128, NH), 256, A_SMEM>>>(q, k, v, ctx);

    // 4) output projection (fp32 out)
    dim3 wo_grid(DM / 128, SEQ / 128, 1);
    gemm_f16<false><<<wo_grid, 256, G_SMEM>>>(ctx, woh, woh, woh, out, out, out, 1.0f);
}